// round 2
// baseline (speedup 1.0000x reference)
#include <cuda_runtime.h>

// Problem shape: activations [B=64, C=256, L=512] float32.
#define C_DIM 256
#define B_DIM 64
#define L_DIM 512
#define N_PER_C (B_DIM * L_DIM)        // 32768 elements per channel
#define F4_PER_ROW (L_DIM / 4)          // 128 float4 per (b,c) row
#define F4_PER_C (N_PER_C / 4)          // 8192 float4 per channel
#define TOTAL_F4 (B_DIM * C_DIM * L_DIM / 4)  // 2097152

// Per-channel affine coefficients produced by the stats kernel:
// y = x * g_scale[c] + g_shift[c]
__device__ float g_scale[C_DIM];
__device__ float g_shift[C_DIM];

// ---------------------------------------------------------------------------
// Kernel 1: per-channel mean / var -> scale & shift.
// One block per channel (256 blocks x 256 threads). Each thread accumulates
// 32 float4 (128 scalars) in fp32 (4 independent lanes -> tiny rounding),
// then the block reduces in fp64 via shared memory.
// ---------------------------------------------------------------------------
__global__ void __launch_bounds__(256) bn_stats_kernel(
    const float* __restrict__ act,
    const float* __restrict__ w,
    const float* __restrict__ bias)
{
    const int c = blockIdx.x;
    const int tid = threadIdx.x;
    const float4* a4 = (const float4*)act;

    float s0 = 0.f, s1 = 0.f, s2 = 0.f, s3 = 0.f;
    float q0 = 0.f, q1 = 0.f, q2 = 0.f, q3 = 0.f;

    #pragma unroll 4
    for (int j = tid; j < F4_PER_C; j += 256) {
        const int bb  = j >> 7;        // batch index
        const int pos = j & 127;       // float4 position within row
        float4 v = a4[bb * (C_DIM * F4_PER_ROW) + c * F4_PER_ROW + pos];
        s0 += v.x; s1 += v.y; s2 += v.z; s3 += v.w;
        q0 = fmaf(v.x, v.x, q0);
        q1 = fmaf(v.y, v.y, q1);
        q2 = fmaf(v.z, v.z, q2);
        q3 = fmaf(v.w, v.w, q3);
    }

    double s = (double)s0 + (double)s1 + (double)s2 + (double)s3;
    double q = (double)q0 + (double)q1 + (double)q2 + (double)q3;

    __shared__ double sh_s[256];
    __shared__ double sh_q[256];
    sh_s[tid] = s;
    sh_q[tid] = q;
    __syncthreads();

    #pragma unroll
    for (int off = 128; off > 0; off >>= 1) {
        if (tid < off) {
            sh_s[tid] += sh_s[tid + off];
            sh_q[tid] += sh_q[tid + off];
        }
        __syncthreads();
    }

    if (tid == 0) {
        const double inv_n = 1.0 / (double)N_PER_C;
        double mean = sh_s[0] * inv_n;
        double var  = sh_q[0] * inv_n - mean * mean;
        double scale = (double)w[c] * rsqrt(var + 1e-5);
        g_scale[c] = (float)scale;
        g_shift[c] = (float)((double)bias[c] - mean * scale);
    }
}

// ---------------------------------------------------------------------------
// 16-step ternary LIF with constant input x, subtract reset.
// Reference recurrence per step:
//   reset = fire(mem)                     // == spk from previous step
//   mem   = 0.9*mem + x - reset
//   spk   = fire(mem);  sum += spk
// fire(m) = (m > 1) - (m < -1)  in {-1, 0, +1}
// Spike computed with one |mem| > 1 compare plus a sign-bit OR:
//   sgn = copysign(1.0f, mem) via (mem & 0x80000000) | 0x3f800000
//   spk = (|mem| > 1) ? sgn : 0
// (strict-inequality semantics match: |mem| > 1 is false at mem == +/-1)
// ---------------------------------------------------------------------------
__device__ __forceinline__ float lif16(float x)
{
    // Step 1 (mem starts at 0, reset = fire(0) = 0): mem = x.
    float mem = x;
    float sgn = __int_as_float((__float_as_int(mem) & 0x80000000) | 0x3f800000);
    float spk = (fabsf(mem) > 1.0f) ? sgn : 0.0f;
    float sum = spk;

    #pragma unroll
    for (int t = 1; t < 16; ++t) {
        mem = fmaf(0.9f, mem, x - spk);
        sgn = __int_as_float((__float_as_int(mem) & 0x80000000) | 0x3f800000);
        spk = (fabsf(mem) > 1.0f) ? sgn : 0.0f;
        sum += spk;
    }
    return sum * 0.0625f;   // mean over 16 steps
}

// ---------------------------------------------------------------------------
// Kernel 2: normalize + LIF scan + write. One float4 per thread (4 independent
// scan chains for ILP). Channel of element e = (e >> 9) & 255; a float4 never
// crosses a channel boundary (L = 512 divisible by 4).
// ---------------------------------------------------------------------------
__global__ void __launch_bounds__(256) lif_kernel(
    const float* __restrict__ act,
    float* __restrict__ out)
{
    const int i = blockIdx.x * 256 + threadIdx.x;   // float4 index
    const int c = (i >> 7) & (C_DIM - 1);           // (4i >> 9) & 255

    const float sc = g_scale[c];
    const float sh = g_shift[c];

    float4 v = ((const float4*)act)[i];
    float4 r;
    r.x = lif16(fmaf(v.x, sc, sh));
    r.y = lif16(fmaf(v.y, sc, sh));
    r.z = lif16(fmaf(v.z, sc, sh));
    r.w = lif16(fmaf(v.w, sc, sh));

    ((float4*)out)[i] = r;
}

// ---------------------------------------------------------------------------
// Launch. Inputs (metadata order): activations, bn_weight, bn_bias.
// ---------------------------------------------------------------------------
extern "C" void kernel_launch(void* const* d_in, const int* in_sizes, int n_in,
                              void* d_out, int out_size)
{
    const float* act  = (const float*)d_in[0];
    const float* w    = (const float*)d_in[1];
    const float* bias = (const float*)d_in[2];
    float* out = (float*)d_out;

    bn_stats_kernel<<<C_DIM, 256>>>(act, w, bias);
    lif_kernel<<<TOTAL_F4 / 256, 256>>>(act, out);
}

// round 5
// speedup vs baseline: 1.5415x; 1.5415x over previous
#include <cuda_runtime.h>
#include <cstring>
#include <cfloat>
#include <cmath>

// Problem shape: activations [B=64, C=256, L=512] float32.
#define C_DIM 256
#define B_DIM 64
#define L_DIM 512
#define N_PER_C (B_DIM * L_DIM)               // 32768 per channel
#define F4_PER_ROW (L_DIM / 4)                // 128
#define F4_PER_C (N_PER_C / 4)                // 8192
#define TOTAL_F4 (B_DIM * C_DIM * L_DIM / 4)  // 2097152

// Per-channel affine coefficients: y = x * g_scale[c] + g_shift[c]
__device__ float g_scale[C_DIM];
__device__ float g_shift[C_DIM];

// ---------------------------------------------------------------------------
// Kernel 1: per-channel mean / var -> scale & shift. (verified in R2)
// ---------------------------------------------------------------------------
__global__ void __launch_bounds__(256) bn_stats_kernel(
    const float* __restrict__ act,
    const float* __restrict__ w,
    const float* __restrict__ bias)
{
    const int c = blockIdx.x;
    const int tid = threadIdx.x;
    const float4* a4 = (const float4*)act;

    float s0 = 0.f, s1 = 0.f, s2 = 0.f, s3 = 0.f;
    float q0 = 0.f, q1 = 0.f, q2 = 0.f, q3 = 0.f;

    #pragma unroll 4
    for (int j = tid; j < F4_PER_C; j += 256) {
        const int bb  = j >> 7;
        const int pos = j & 127;
        float4 v = a4[bb * (C_DIM * F4_PER_ROW) + c * F4_PER_ROW + pos];
        s0 += v.x; s1 += v.y; s2 += v.z; s3 += v.w;
        q0 = fmaf(v.x, v.x, q0);
        q1 = fmaf(v.y, v.y, q1);
        q2 = fmaf(v.z, v.z, q2);
        q3 = fmaf(v.w, v.w, q3);
    }

    double s = (double)s0 + (double)s1 + (double)s2 + (double)s3;
    double q = (double)q0 + (double)q1 + (double)q2 + (double)q3;

    __shared__ double sh_s[256];
    __shared__ double sh_q[256];
    sh_s[tid] = s;
    sh_q[tid] = q;
    __syncthreads();

    #pragma unroll
    for (int off = 128; off > 0; off >>= 1) {
        if (tid < off) {
            sh_s[tid] += sh_s[tid + off];
            sh_q[tid] += sh_q[tid + off];
        }
        __syncthreads();
    }

    if (tid == 0) {
        const double inv_n = 1.0 / (double)N_PER_C;
        double mean = sh_s[0] * inv_n;
        double var  = sh_q[0] * inv_n - mean * mean;
        double scale = (double)w[c] * rsqrt(var + 1e-5);
        g_scale[c] = (float)scale;
        g_shift[c] = (float)((double)bias[c] - mean * scale);
    }
}

// ---------------------------------------------------------------------------
// Fallback: verified 16-step scan (R2, rel_err 0.0).
// ---------------------------------------------------------------------------
__device__ __forceinline__ float lif16(float x)
{
    float mem = x;
    float sgn = __int_as_float((__float_as_int(mem) & 0x80000000) | 0x3f800000);
    float spk = (fabsf(mem) > 1.0f) ? sgn : 0.0f;
    float sum = spk;

    #pragma unroll
    for (int t = 1; t < 16; ++t) {
        mem = fmaf(0.9f, mem, x - spk);
        sgn = __int_as_float((__float_as_int(mem) & 0x80000000) | 0x3f800000);
        spk = (fabsf(mem) > 1.0f) ? sgn : 0.0f;
        sum += spk;
    }
    return sum * 0.0625f;
}

__global__ void __launch_bounds__(256) lif_kernel(
    const float* __restrict__ act,
    float* __restrict__ out)
{
    const int i = blockIdx.x * 256 + threadIdx.x;
    const int c = (i >> 7) & (C_DIM - 1);

    const float sc = g_scale[c];
    const float sh = g_shift[c];

    float4 v = ((const float4*)act)[i];
    float4 r;
    r.x = lif16(fmaf(v.x, sc, sh));
    r.y = lif16(fmaf(v.y, sc, sh));
    r.z = lif16(fmaf(v.z, sc, sh));
    r.w = lif16(fmaf(v.w, sc, sh));

    ((float4*)out)[i] = r;
}

// ---------------------------------------------------------------------------
// Lookup-table path. The 16-step LIF is a pure odd function f(x), piecewise
// constant in |x|. Table built on host at capture time (bit-exact replica of
// lif16), passed by value as a kernel parameter (512 B, graph-safe).
//   edges[i] = largest fp32 belonging to piece i (padded with FLT_MAX)
//   vals[i]  = value of piece i                  (padded with last value)
// ---------------------------------------------------------------------------
struct LifTab {
    float e[64];
    float v[64];
};

__global__ void __launch_bounds__(256) lif_lut_kernel(
    const float* __restrict__ act,
    float* __restrict__ out,
    const LifTab tab)
{
    __shared__ float se[64];
    __shared__ float sv[64];
    if (threadIdx.x < 64) {
        se[threadIdx.x] = tab.e[threadIdx.x];
        sv[threadIdx.x] = tab.v[threadIdx.x];
    }
    __syncthreads();

    const int i = blockIdx.x * 256 + threadIdx.x;   // float4 index
    const int c = (i >> 7) & (C_DIM - 1);

    const float sc = g_scale[c];
    const float sh = g_shift[c];

    float4 v = ((const float4*)act)[i];
    float xs[4] = { fmaf(v.x, sc, sh), fmaf(v.y, sc, sh),
                    fmaf(v.z, sc, sh), fmaf(v.w, sc, sh) };
    float r[4];

    #pragma unroll
    for (int k = 0; k < 4; ++k) {
        const float a = fabsf(xs[k]);
        int pos = 0;
        #pragma unroll
        for (int s = 32; s > 0; s >>= 1)
            if (se[pos + s - 1] < a) pos += s;       // lower_bound: #edges < a
        const float val = sv[pos];
        r[k] = __int_as_float(__float_as_int(val) |
                              (__float_as_int(xs[k]) & 0x80000000));
    }

    ((float4*)out)[i] = make_float4(r[0], r[1], r[2], r[3]);
}

// ---------------------------------------------------------------------------
// Host-side bit-exact replica of lif16 (fmaf == device FFMA, IEEE fp32).
// ---------------------------------------------------------------------------
static float host_lif16(float x)
{
    float mem = x;
    float spk = (fabsf(mem) > 1.0f) ? copysignf(1.0f, mem) : 0.0f;
    float sum = spk;
    for (int t = 1; t < 16; ++t) {
        mem = fmaf(0.9f, mem, x - spk);
        spk = (fabsf(mem) > 1.0f) ? copysignf(1.0f, mem) : 0.0f;
        sum += spk;
    }
    return sum * 0.0625f;
}

static inline unsigned f2u(float f) { unsigned u; std::memcpy(&u, &f, 4); return u; }
static inline float u2f(unsigned u) { float f; std::memcpy(&f, &u, 4); return f; }

// Bisect to the largest fp32 in [lo, hi) with f == vlo (positive floats:
// bit pattern ordering is monotone). Bounded iterations (paranoia).
static float host_bisect_edge(float lo, float hi, float vlo)
{
    for (int it = 0; it < 64; ++it) {
        unsigned a = f2u(lo), b = f2u(hi);
        if (b - a <= 1u) break;
        float m = u2f(a + (b - a) / 2u);
        if (host_lif16(m) == vlo) lo = m; else hi = m;
    }
    return lo;
}

// Host replica of the device table lookup (positive a).
static float host_lut_eval(const LifTab& tab, float a)
{
    int pos = 0;
    for (int s = 32; s > 0; s >>= 1)
        if (tab.e[pos + s - 1] < a) pos += s;
    return tab.v[pos];
}

// Build table. Returns piece count, or -1 on overflow/validation failure.
static int host_build_table(LifTab& tab)
{
    int K = 0;                       // number of edges recorded
    float cur = host_lif16(0.0f);    // value of piece 0 (== 0)
    float px = 0.0f;
    float vals[96];
    float edges[96];
    vals[0] = cur;

    bool overflow = false;
    auto feed = [&](float x) {
        float fv = host_lif16(x);
        if (fv != cur) {
            if (K < 90) {
                edges[K] = host_bisect_edge(px, x, cur);
                ++K;
                vals[K] = fv;
            } else {
                overflow = true;
            }
            cur = fv;
        }
        px = x;
    };

    // Dense sweep over [0, 1.25]: all breakpoints live in ~[0.12, 1.1].
    const int N1 = 1 << 20;
    for (int j = 1; j <= N1; ++j) {
        float x = 1.25f * ((float)j * (1.0f / (float)N1));
        feed(x);
    }
    // Coarse tail to ~16 (expected constant f == 1; catches surprises).
    for (int j = 1; j <= 15104; ++j) {
        float x = 1.25f + (float)j * 0.0009765625f;  // step 1/1024
        feed(x);
    }

    if (overflow || K > 63) return -1;

    for (int i = K; i < 64; ++i) tab.e[i] = FLT_MAX;
    for (int i = 0; i < K; ++i)  tab.e[i] = edges[i];
    for (int i = 0; i <= K; ++i) tab.v[i] = vals[i];
    for (int i = K + 1; i < 64; ++i) tab.v[i] = vals[K];

    // ---- Validation: table must reproduce host_lif16 exactly at every
    // recorded edge (both sides, +/-1 ulp) and on an interior probe grid.
    for (int i = 0; i < K; ++i) {
        float e  = tab.e[i];
        float eu = u2f(f2u(e) + 1u);   // next float above the edge
        if (host_lut_eval(tab, e)  != host_lif16(e))  return -1;
        if (host_lut_eval(tab, eu) != host_lif16(eu)) return -1;
    }
    for (int j = 0; j <= 4096; ++j) {
        float x = 1.25f * ((float)j / 4096.0f);
        if (host_lut_eval(tab, x) != host_lif16(x)) return -1;
    }
    for (int j = 0; j <= 256; ++j) {
        float x = 1.25f + 14.75f * ((float)j / 256.0f);
        if (host_lut_eval(tab, x) != host_lif16(x)) return -1;
    }
    return K + 1;
}

// ---------------------------------------------------------------------------
// Launch. Inputs (metadata order): activations, bn_weight, bn_bias.
// ---------------------------------------------------------------------------
extern "C" void kernel_launch(void* const* d_in, const int* in_sizes, int n_in,
                              void* d_out, int out_size)
{
    const float* act  = (const float*)d_in[0];
    const float* w    = (const float*)d_in[1];
    const float* bias = (const float*)d_in[2];
    float* out = (float*)d_out;

    bn_stats_kernel<<<C_DIM, 256>>>(act, w, bias);

    LifTab tab;
    int K = host_build_table(tab);   // input-independent, deterministic

    if (K > 0) {
        lif_lut_kernel<<<TOTAL_F4 / 256, 256>>>(act, out, tab);
    } else {
        lif_kernel<<<TOTAL_F4 / 256, 256>>>(act, out);  // verified fallback
    }
}